// round 3
// baseline (speedup 1.0000x reference)
#include <cuda_runtime.h>
#include <math.h>

#define NTOK 2048
#define HDIM 2048
#define NPROJ 17536
#define COL_K 1024
#define COL_V 1088
#define COL_FF 1152
#define COL_GATE 9344
#define FFI 8192
#define AI 1024
#define NHEADS 16
#define QSCALE 0.125f
#define LN_EPS 1e-5f

// ---------------- scratch (static device globals; no allocation) ----------------
__device__ float  g_xn[(size_t)NTOK * HDIM];        // 16 MB
__device__ float  g_proj[(size_t)NTOK * NPROJ];     // 143 MB
__device__ float  g_attn[(size_t)NTOK * AI];        // 8 MB
__device__ float  g_ffg[(size_t)NTOK * FFI];        // 64 MB
__device__ float  g_suff[NTOK * 64];
__device__ double g_part[256];
__device__ float  g_scale;

// ---------------- f32x2 helpers ----------------
__device__ __forceinline__ void fma2(unsigned long long& acc, unsigned long long a, unsigned long long b) {
    asm("fma.rn.f32x2 %0, %1, %2, %0;" : "+l"(acc) : "l"(a), "l"(b));
}
__device__ __forceinline__ unsigned long long pack2(float x, float y) {
    unsigned long long r;
    asm("mov.b64 %0, {%1, %2};" : "=l"(r) : "f"(x), "f"(y));
    return r;
}

// ---------------- global-RMS layernorm (scale is a single scalar) ----------------
__global__ void k_sumsq(const float* __restrict__ x) {
    const int n = NTOK * HDIM;
    double acc = 0.0;
    for (int i = blockIdx.x * blockDim.x + threadIdx.x; i < n; i += gridDim.x * blockDim.x) {
        float v = x[i];
        acc += (double)v * (double)v;
    }
    __shared__ double s[256];
    s[threadIdx.x] = acc;
    __syncthreads();
    for (int o = 128; o > 0; o >>= 1) {
        if (threadIdx.x < o) s[threadIdx.x] += s[threadIdx.x + o];
        __syncthreads();
    }
    if (threadIdx.x == 0) g_part[blockIdx.x] = s[0];
}

__global__ void k_finalize() {
    __shared__ double s[256];
    s[threadIdx.x] = g_part[threadIdx.x];
    __syncthreads();
    for (int o = 128; o > 0; o >>= 1) {
        if (threadIdx.x < o) s[threadIdx.x] += s[threadIdx.x + o];
        __syncthreads();
    }
    if (threadIdx.x == 0) {
        double mean = s[0] / (double)(NTOK * HDIM);
        g_scale = (float)(1.0 / sqrt(mean)) + LN_EPS;
    }
}

__global__ void k_norm(const float* __restrict__ x, const float* __restrict__ nw) {
    int i = blockIdx.x * blockDim.x + threadIdx.x;
    if (i < NTOK * HDIM) {
        g_xn[i] = x[i] * g_scale * nw[i & (HDIM - 1)];
    }
}

// ---------------- SGEMM: C[M,N] = A[M,K] @ B[K,N] (+C if ACC), f32x2 inner ----------------
// BM=BN=128, BK=16, TM=TN=8, 256 threads. All dims multiples of tiles.
template <int ACC>
__global__ void __launch_bounds__(256) k_gemm(const float* __restrict__ A,
                                              const float* __restrict__ B,
                                              float* __restrict__ C,
                                              int M, int N, int K) {
    __shared__ float As[16][132];   // transposed A tile, padded
    __shared__ float Bs[16][128];

    const int tid = threadIdx.x;
    const int tx = tid & 15;        // n-dir
    const int ty = tid >> 4;        // m-dir
    const int bm = blockIdx.y * 128;
    const int bn = blockIdx.x * 128;

    const int arow = tid >> 2;          // 0..63
    const int acol = (tid & 3) * 4;     // 0..12
    const int brow = tid >> 5;          // 0..7
    const int bcol = (tid & 31) * 4;    // 0..124

    unsigned long long acc[8][4];
#pragma unroll
    for (int i = 0; i < 8; i++)
#pragma unroll
        for (int j = 0; j < 4; j++) acc[i][j] = 0ULL;   // (+0.f, +0.f)

    for (int k0 = 0; k0 < K; k0 += 16) {
        float4 a0 = *(const float4*)(A + (size_t)(bm + arow) * K + k0 + acol);
        float4 a1 = *(const float4*)(A + (size_t)(bm + arow + 64) * K + k0 + acol);
        float4 b0 = *(const float4*)(B + (size_t)(k0 + brow) * N + bn + bcol);
        float4 b1 = *(const float4*)(B + (size_t)(k0 + brow + 8) * N + bn + bcol);

        __syncthreads();
        As[acol + 0][arow] = a0.x; As[acol + 1][arow] = a0.y;
        As[acol + 2][arow] = a0.z; As[acol + 3][arow] = a0.w;
        As[acol + 0][arow + 64] = a1.x; As[acol + 1][arow + 64] = a1.y;
        As[acol + 2][arow + 64] = a1.z; As[acol + 3][arow + 64] = a1.w;
        *(float4*)&Bs[brow][bcol] = b0;
        *(float4*)&Bs[brow + 8][bcol] = b1;
        __syncthreads();

#pragma unroll
        for (int kk = 0; kk < 16; ++kk) {
            float4 av0 = *(const float4*)&As[kk][ty * 8];
            float4 av1 = *(const float4*)&As[kk][ty * 8 + 4];
            const unsigned long long* bp = (const unsigned long long*)&Bs[kk][tx * 8];
            unsigned long long b0p = bp[0], b1p = bp[1], b2p = bp[2], b3p = bp[3];
            float a[8] = {av0.x, av0.y, av0.z, av0.w, av1.x, av1.y, av1.z, av1.w};
#pragma unroll
            for (int i = 0; i < 8; i++) {
                unsigned long long ap = pack2(a[i], a[i]);
                fma2(acc[i][0], ap, b0p);
                fma2(acc[i][1], ap, b1p);
                fma2(acc[i][2], ap, b2p);
                fma2(acc[i][3], ap, b3p);
            }
        }
    }

#pragma unroll
    for (int i = 0; i < 8; i++) {
        size_t rowoff = (size_t)(bm + ty * 8 + i) * N + bn + tx * 8;
#pragma unroll
        for (int j = 0; j < 4; j++) {
            float2 v = *(float2*)&acc[i][j];
            if (ACC) {
                float2 o = *(const float2*)&C[rowoff + 2 * j];
                v.x += o.x; v.y += o.y;
            }
            *(float2*)&C[rowoff + 2 * j] = v;
        }
    }
}

// ---------------- RoPE on k (in place in g_proj) ----------------
__global__ void k_rope_k(const float* __restrict__ sn, const float* __restrict__ cs) {
    int idx = blockIdx.x * blockDim.x + threadIdx.x;   // 2048 * 32
    if (idx >= NTOK * 32) return;
    int row = idx >> 5, p = idx & 31;
    float* kr = g_proj + (size_t)row * NPROJ + COL_K;
    float x1 = kr[2 * p], x2 = kr[2 * p + 1];
    int base = row * 64;
    float c0 = cs[base + 2 * p],     s0 = sn[base + 2 * p];
    float c1 = cs[base + 2 * p + 1], s1 = sn[base + 2 * p + 1];
    kr[2 * p]     = x1 * c0 - x2 * s0;
    kr[2 * p + 1] = x2 * c1 + x1 * s1;
}

// ---------------- swish gate ----------------
__global__ void k_swish() {
    int i = blockIdx.x * blockDim.x + threadIdx.x;     // 2048 * 8192
    if (i >= NTOK * FFI) return;
    int row = i >> 13, c = i & (FFI - 1);
    const float* pr = g_proj + (size_t)row * NPROJ;
    float f = pr[COL_FF + c];
    float g = pr[COL_GATE + c];
    g_ffg[i] = f * (g / (1.0f + expf(-g)));
}

// ---------------- attention: suffix means for rows < N-1 ----------------
// Faithful to reference numerics: masked positions carry +1e9 -> softmax weight is
// exactly 1/(N-1-i) on future positions (exp(sim-1e9) underflows to exact +0).
__global__ void k_suffix() {
    int d = threadIdx.x;   // 64 threads
    double acc = 0.0;
    for (int i = NTOK - 2; i >= 0; --i) {
        acc += (double)g_proj[(size_t)(i + 1) * NPROJ + COL_V + d];
        g_suff[i * 64 + d] = (float)acc;
    }
}

__global__ void k_fill_attn() {
    int idx = blockIdx.x * blockDim.x + threadIdx.x;   // (NTOK-1) * 1024
    if (idx >= (NTOK - 1) * AI) return;
    int row = idx >> 10, col = idx & (AI - 1);
    int d = col & 63;
    float inv = 1.0f / (float)(NTOK - 1 - row);
    g_attn[(size_t)row * AI + col] = g_suff[row * 64 + d] * inv;
}

// ---------------- attention: real softmax for the last row (per head) ----------------
__global__ void k_lastrow(const float* __restrict__ sn, const float* __restrict__ cs) {
    __shared__ float q[64];
    __shared__ float sv[NTOK];
    __shared__ float red[16];
    __shared__ float ored[4][64];

    int h = blockIdx.x;
    int tid = threadIdx.x, w = tid >> 5, l = tid & 31;

    if (tid < 32) {
        const float* qrow = g_proj + (size_t)(NTOK - 1) * NPROJ + h * 64;
        float x1 = qrow[2 * tid] * QSCALE;
        float x2 = qrow[2 * tid + 1] * QSCALE;
        int base = (NTOK - 1) * 64;
        q[2 * tid]     = x1 * cs[base + 2 * tid]     - x2 * sn[base + 2 * tid];
        q[2 * tid + 1] = x2 * cs[base + 2 * tid + 1] + x1 * sn[base + 2 * tid + 1];
    }
    __syncthreads();

    // scores (k already roped in g_proj)
    for (int j = w; j < NTOK; j += 4) {
        const float* kr = g_proj + (size_t)j * NPROJ + COL_K;
        float p = q[l] * kr[l] + q[l + 32] * kr[l + 32];
#pragma unroll
        for (int o = 16; o; o >>= 1) p += __shfl_xor_sync(0xffffffffu, p, o);
        if (l == 0) sv[j] = p;
    }
    __syncthreads();

    // max
    float m = -1e30f;
    for (int j = tid; j < NTOK; j += 128) m = fmaxf(m, sv[j]);
#pragma unroll
    for (int o = 16; o; o >>= 1) m = fmaxf(m, __shfl_xor_sync(0xffffffffu, m, o));
    if (l == 0) red[w] = m;
    __syncthreads();
    m = fmaxf(fmaxf(red[0], red[1]), fmaxf(red[2], red[3]));
    __syncthreads();

    // exp + sum
    float ssum = 0.0f;
    for (int j = tid; j < NTOK; j += 128) {
        float p = expf(sv[j] - m);
        sv[j] = p;
        ssum += p;
    }
#pragma unroll
    for (int o = 16; o; o >>= 1) ssum += __shfl_xor_sync(0xffffffffu, ssum, o);
    if (l == 0) red[8 + w] = ssum;
    __syncthreads();
    ssum = red[8] + red[9] + red[10] + red[11];

    // weighted sum of v
    float o0 = 0.0f, o1 = 0.0f;
    for (int j = w; j < NTOK; j += 4) {
        const float* vr = g_proj + (size_t)j * NPROJ + COL_V;
        float p = sv[j];
        o0 += p * vr[l];
        o1 += p * vr[l + 32];
    }
    ored[w][l] = o0;
    ored[w][l + 32] = o1;
    __syncthreads();
    if (tid < 64) {
        float r = (ored[0][tid] + ored[1][tid] + ored[2][tid] + ored[3][tid]) / ssum;
        g_attn[(size_t)(NTOK - 1) * AI + h * 64 + tid] = r;
    }
}

// ---------------- launch ----------------
extern "C" void kernel_launch(void* const* d_in, const int* in_sizes, int n_in,
                              void* d_out, int out_size) {
    const float* x       = (const float*)d_in[0];
    const float* wi      = (const float*)d_in[1];
    const float* attn_wo = (const float*)d_in[2];
    const float* ff_wo   = (const float*)d_in[3];
    const float* nw      = (const float*)d_in[4];
    const float* sn      = (const float*)d_in[5];
    const float* cs      = (const float*)d_in[6];
    float* out = (float*)d_out;

    float *p_xn, *p_proj, *p_attn, *p_ffg;
    cudaGetSymbolAddress((void**)&p_xn, g_xn);
    cudaGetSymbolAddress((void**)&p_proj, g_proj);
    cudaGetSymbolAddress((void**)&p_attn, g_attn);
    cudaGetSymbolAddress((void**)&p_ffg, g_ffg);

    // 1) global-RMS layernorm
    k_sumsq<<<256, 256>>>(x);
    k_finalize<<<1, 256>>>();
    k_norm<<<(NTOK * HDIM + 255) / 256, 256>>>(x, nw);

    // 2) fused projection: proj = xn @ wi   [2048 x 17536]
    {
        dim3 g(NPROJ / 128, NTOK / 128);
        k_gemm<0><<<g, 256>>>(p_xn, wi, p_proj, NTOK, NPROJ, HDIM);
    }

    // 3) RoPE on k, swish gate, attention
    k_rope_k<<<(NTOK * 32 + 255) / 256, 256>>>(sn, cs);
    k_swish<<<(NTOK * FFI + 255) / 256, 256>>>();
    k_suffix<<<1, 64>>>();
    k_fill_attn<<<((NTOK - 1) * AI + 255) / 256, 256>>>();
    k_lastrow<<<NHEADS, 128>>>(sn, cs);

    // 4) output GEMMs: out = attn @ attn_wo ; out += ffg @ ff_wo
    {
        dim3 g(HDIM / 128, NTOK / 128);
        k_gemm<0><<<g, 256>>>(p_attn, attn_wo, out, NTOK, HDIM, AI);
        k_gemm<1><<<g, 256>>>(p_ffg, ff_wo, out, NTOK, HDIM, FFI);
    }
}

// round 7
// speedup vs baseline: 4.0186x; 4.0186x over previous
#include <cuda_runtime.h>
#include <cuda_fp16.h>
#include <cstdint>
#include <math.h>

#define NTOK 2048
#define HDIM 2048
#define NPROJ 17536
#define COL_K 1024
#define COL_V 1088
#define COL_FF 1152
#define COL_GATE 9344
#define FFI 8192
#define AI 1024
#define NHEADS 16
#define QSCALE 0.125f
#define LN_EPS 1e-5f

// ---------------- scratch (static device globals; no allocation) ----------------
__device__ float  g_proj[(size_t)NTOK * NPROJ];      // 143 MB fp32
__device__ __half g_xn[(size_t)NTOK * HDIM];         // normalized x, fp16
__device__ __half g_wT_h[(size_t)NPROJ * HDIM];      // wi^T hi [17536,2048]
__device__ __half g_wT_l[(size_t)NPROJ * HDIM];      // wi^T lo
__device__ __half g_ffwT_h[(size_t)HDIM * FFI];      // ff_wo^T hi [2048,8192]
__device__ __half g_ffwT_l[(size_t)HDIM * FFI];
__device__ __half g_awT_h[(size_t)HDIM * AI];        // attn_wo^T hi [2048,1024]
__device__ __half g_awT_l[(size_t)HDIM * AI];
__device__ __half g_ffg[(size_t)NTOK * FFI];         // gated ff activations, fp16
__device__ __half g_attn[(size_t)NTOK * AI];         // attention output, fp16
__device__ float  g_suff[NTOK * 64];
__device__ double g_segsum[32 * 64];
__device__ double g_segoff[32 * 64];
__device__ double g_part[256];
__device__ float  g_scale;

// ---------------- helpers ----------------
__device__ __forceinline__ uint32_t smem_u32(const void* p) {
    uint32_t a;
    asm("{ .reg .u64 t; cvta.to.shared.u64 t, %1; cvt.u32.u64 %0, t; }" : "=r"(a) : "l"(p));
    return a;
}
__device__ __forceinline__ void cp16(uint32_t dst, const void* src) {
    asm volatile("cp.async.cg.shared.global [%0], [%1], 16;" :: "r"(dst), "l"(src));
}
__device__ __forceinline__ void ldsm4(uint32_t* r, uint32_t addr) {
    asm volatile("ldmatrix.sync.aligned.m8n8.x4.shared.b16 {%0,%1,%2,%3}, [%4];"
                 : "=r"(r[0]), "=r"(r[1]), "=r"(r[2]), "=r"(r[3]) : "r"(addr));
}
__device__ __forceinline__ void mma16816(float* c, const uint32_t* a, const uint32_t* b) {
    asm volatile("mma.sync.aligned.m16n8k16.row.col.f32.f16.f16.f32 "
                 "{%0,%1,%2,%3}, {%4,%5,%6,%7}, {%8,%9}, {%0,%1,%2,%3};"
                 : "+f"(c[0]), "+f"(c[1]), "+f"(c[2]), "+f"(c[3])
                 : "r"(a[0]), "r"(a[1]), "r"(a[2]), "r"(a[3]), "r"(b[0]), "r"(b[1]));
}
__device__ __forceinline__ void splith(float v, __half& h, __half& l) {
    h = __float2half_rn(v);
    l = __float2half_rn(v - __half2float(h));
}

// ================= layernorm (global RMS scalar) =================
__global__ void k_sumsq(const float* __restrict__ x) {
    const int n = NTOK * HDIM;
    double acc = 0.0;
    for (int i = blockIdx.x * blockDim.x + threadIdx.x; i < n; i += gridDim.x * blockDim.x) {
        float v = x[i];
        acc += (double)v * (double)v;
    }
    __shared__ double s[256];
    s[threadIdx.x] = acc;
    __syncthreads();
    for (int o = 128; o > 0; o >>= 1) {
        if (threadIdx.x < o) s[threadIdx.x] += s[threadIdx.x + o];
        __syncthreads();
    }
    if (threadIdx.x == 0) g_part[blockIdx.x] = s[0];
}

__global__ void k_finalize() {
    __shared__ double s[256];
    s[threadIdx.x] = g_part[threadIdx.x];
    __syncthreads();
    for (int o = 128; o > 0; o >>= 1) {
        if (threadIdx.x < o) s[threadIdx.x] += s[threadIdx.x + o];
        __syncthreads();
    }
    if (threadIdx.x == 0) {
        double mean = s[0] / (double)(NTOK * HDIM);
        g_scale = (float)(1.0 / sqrt(mean)) + LN_EPS;
    }
}

__global__ void k_norm_h(const float* __restrict__ x, const float* __restrict__ nw) {
    int i = blockIdx.x * blockDim.x + threadIdx.x;
    if (i < NTOK * HDIM) {
        float v = x[i] * g_scale * nw[i & (HDIM - 1)];
        g_xn[i] = __float2half_rn(v);
    }
}

// ================= weight transpose + split: W[K,N] fp32 -> WT[N,K] fp16 hi/lo =================
__global__ void k_transplit(const float* __restrict__ W, __half* __restrict__ Th,
                            __half* __restrict__ Tl, int K, int N) {
    __shared__ float t[32][33];
    int n0 = blockIdx.x * 32, k0 = blockIdx.y * 32;
    int tx = threadIdx.x & 31, ty = threadIdx.x >> 5;
#pragma unroll
    for (int r = 0; r < 4; r++)
        t[ty * 4 + r][tx] = W[(size_t)(k0 + ty * 4 + r) * N + n0 + tx];
    __syncthreads();
#pragma unroll
    for (int r = 0; r < 4; r++) {
        float v = t[tx][ty * 4 + r];
        size_t o = (size_t)(n0 + ty * 4 + r) * K + k0 + tx;
        __half h, l;
        splith(v, h, l);
        Th[o] = h;
        Tl[o] = l;
    }
}

// ================= HMMA fp16 GEMM with split-B =================
// C[M,N] = A @ (Bh + Bl)^T, fp32 accum. A [M,K] fp16 K-major, B* [N,K] fp16 K-major.
// CTA 128x128, BK=64, 8 warps (2x4), warp tile 64x32, 3-stage cp.async pipeline.
#define PLANEB 16384               // 128 rows x 128B per operand tile
#define STAGEB (3 * PLANEB)        // A, Bh, Bl
#define NSTAGES 3
#define SMEM_GEMM (NSTAGES * STAGEB)   // 147456 bytes

__device__ __forceinline__ void load_plane(uint32_t sdst, const __half* __restrict__ g,
                                           int K, int k0, int tid) {
#pragma unroll
    for (int it = 0; it < 4; it++) {
        int idx = tid + it * 256;
        int row = idx >> 3, ch = idx & 7;
        uint32_t off = (uint32_t)(row << 7) + (uint32_t)((ch ^ (row & 7)) << 4);
        cp16(sdst + off, g + (size_t)row * K + k0 + ch * 8);
    }
}

template <int ACCUM>
__global__ void __launch_bounds__(256) k_tgemm(
    const __half* __restrict__ A, const __half* __restrict__ Bh,
    const __half* __restrict__ Bl, float* __restrict__ C,
    int M, int N, int K)
{
    extern __shared__ char smem[];
    const uint32_t sb = smem_u32(smem);
    const int tid = threadIdx.x;
    const int lane = tid & 31, wid = tid >> 5;
    const int wm = wid & 1, wn = wid >> 1;       // warp grid 2(M) x 4(N)
    const int bm = blockIdx.y * 128, bn = blockIdx.x * 128;
    const int NC = K >> 6;

    const __half* Ap  = A  + (size_t)bm * K;
    const __half* Bhp = Bh + (size_t)bn * K;
    const __half* Blp = Bl + (size_t)bn * K;

    float acc[4][4][4];
#pragma unroll
    for (int i = 0; i < 4; i++)
#pragma unroll
        for (int j = 0; j < 4; j++)
#pragma unroll
            for (int q = 0; q < 4; q++) acc[i][j][q] = 0.0f;

    // prologue: stages 0..1
#pragma unroll
    for (int s = 0; s < NSTAGES - 1; s++) {
        uint32_t st = sb + s * STAGEB;
        load_plane(st,              Ap,  K, s * 64, tid);
        load_plane(st + PLANEB,     Bhp, K, s * 64, tid);
        load_plane(st + 2 * PLANEB, Blp, K, s * 64, tid);
        asm volatile("cp.async.commit_group;" ::: "memory");
    }

    // per-thread ldmatrix address components
    // A: rows wm*64 + mt*16 + (lane&15), chunk = ks*2 + (lane>>4)
    int a_row[4], a_cx[4];
#pragma unroll
    for (int mt = 0; mt < 4; mt++) {
        int r = wm * 64 + mt * 16 + (lane & 15);
        a_row[mt] = r << 7;
        a_cx[mt] = r & 7;
    }
    const int a_hi = lane >> 4;
    // B: rows wn*32 + nt2*16 + (lane&7) + ((lane>>4)<<3), chunk = ks*2 + ((lane>>3)&1)
    int b_row[2], b_cx[2];
#pragma unroll
    for (int nt2 = 0; nt2 < 2; nt2++) {
        int r = wn * 32 + nt2 * 16 + (lane & 7) + ((lane >> 4) << 3);
        b_row[nt2] = r << 7;
        b_cx[nt2] = r & 7;
    }
    const int b_hi = (lane >> 3) & 1;

    for (int c = 0; c < NC; c++) {
        asm volatile("cp.async.wait_group 1;" ::: "memory");
        __syncthreads();

        if (c + NSTAGES - 1 < NC) {
            int s = (c + NSTAGES - 1) % NSTAGES;
            uint32_t st = sb + s * STAGEB;
            int k0 = (c + NSTAGES - 1) * 64;
            load_plane(st,              Ap,  K, k0, tid);
            load_plane(st + PLANEB,     Bhp, K, k0, tid);
            load_plane(st + 2 * PLANEB, Blp, K, k0, tid);
        }
        asm volatile("cp.async.commit_group;" ::: "memory");

        const uint32_t stA  = sb + (c % NSTAGES) * STAGEB;
        const uint32_t stBh = stA + PLANEB;
        const uint32_t stBl = stA + 2 * PLANEB;

#pragma unroll
        for (int ks = 0; ks < 4; ks++) {
            uint32_t a[4][4], bh[2][4], bl[2][4];
#pragma unroll
            for (int mt = 0; mt < 4; mt++) {
                uint32_t addr = stA + a_row[mt] + (((ks * 2 + a_hi) ^ a_cx[mt]) << 4);
                ldsm4(a[mt], addr);
            }
#pragma unroll
            for (int nt2 = 0; nt2 < 2; nt2++) {
                uint32_t cpart = (uint32_t)(ks * 2 + b_hi);
                ldsm4(bh[nt2], stBh + b_row[nt2] + ((cpart ^ b_cx[nt2]) << 4));
                ldsm4(bl[nt2], stBl + b_row[nt2] + ((cpart ^ b_cx[nt2]) << 4));
            }
#pragma unroll
            for (int mt = 0; mt < 4; mt++)
#pragma unroll
                for (int nt = 0; nt < 4; nt++) {
                    mma16816(acc[mt][nt], a[mt], &bh[nt >> 1][(nt & 1) * 2]);
                    mma16816(acc[mt][nt], a[mt], &bl[nt >> 1][(nt & 1) * 2]);
                }
        }
    }
    asm volatile("cp.async.wait_group 0;" ::: "memory");

    // epilogue
    const int er = lane >> 2, ec = (lane & 3) * 2;
#pragma unroll
    for (int mt = 0; mt < 4; mt++) {
#pragma unroll
        for (int half = 0; half < 2; half++) {
            int row = bm + wm * 64 + mt * 16 + er + half * 8;
            float* cp = C + (size_t)row * N + bn + wn * 32 + ec;
#pragma unroll
            for (int nt = 0; nt < 4; nt++) {
                float2 v;
                v.x = acc[mt][nt][half * 2 + 0];
                v.y = acc[mt][nt][half * 2 + 1];
                if (ACCUM) {
                    float2 o = *(const float2*)(cp + nt * 8);
                    v.x += o.x; v.y += o.y;
                }
                *(float2*)(cp + nt * 8) = v;
            }
        }
    }
}

// ================= RoPE on k (fp32, in place in g_proj) =================
__global__ void k_rope_k(const float* __restrict__ sn, const float* __restrict__ cs) {
    int idx = blockIdx.x * blockDim.x + threadIdx.x;
    if (idx >= NTOK * 32) return;
    int row = idx >> 5, p = idx & 31;
    float* kr = g_proj + (size_t)row * NPROJ + COL_K;
    float x1 = kr[2 * p], x2 = kr[2 * p + 1];
    int base = row * 64;
    float c0 = cs[base + 2 * p],     s0 = sn[base + 2 * p];
    float c1 = cs[base + 2 * p + 1], s1 = sn[base + 2 * p + 1];
    kr[2 * p]     = x1 * c0 - x2 * s0;
    kr[2 * p + 1] = x2 * c1 + x1 * s1;
}

// ================= swish gate -> fp16 =================
__global__ void k_swish_h() {
    int i = blockIdx.x * blockDim.x + threadIdx.x;
    if (i >= NTOK * FFI) return;
    int row = i >> 13, c = i & (FFI - 1);
    const float* pr = g_proj + (size_t)row * NPROJ;
    float f = pr[COL_FF + c];
    float g = pr[COL_GATE + c];
    g_ffg[i] = __float2half_rn(f * (g / (1.0f + expf(-g))));
}

// ================= suffix scan of v (3-stage parallel) =================
// Faithful to +1e9 mask: softmax weights are exactly 1/(N-1-i) on future positions.
__global__ void k_seg_sum() {
    int s = blockIdx.x, d = threadIdx.x;
    double acc = 0.0;
    for (int j = s * 64; j < s * 64 + 64; j++)
        acc += (double)g_proj[(size_t)j * NPROJ + COL_V + d];
    g_segsum[s * 64 + d] = acc;
}
__global__ void k_seg_off() {
    int d = threadIdx.x;
    double acc = 0.0;
    for (int s = 31; s >= 0; s--) {
        g_segoff[s * 64 + d] = acc;
        acc += g_segsum[s * 64 + d];
    }
}
__global__ void k_seg_suffix() {
    int s = blockIdx.x, d = threadIdx.x;
    double acc = g_segoff[s * 64 + d];
    for (int j = s * 64 + 63; j >= s * 64; j--) {
        acc += (double)g_proj[(size_t)j * NPROJ + COL_V + d];
        if (j >= 1) g_suff[(j - 1) * 64 + d] = (float)acc;
    }
}

__global__ void k_fill_attn_h() {
    int idx = blockIdx.x * blockDim.x + threadIdx.x;
    if (idx >= (NTOK - 1) * AI) return;
    int row = idx >> 10, col = idx & (AI - 1);
    int d = col & 63;
    float inv = 1.0f / (float)(NTOK - 1 - row);
    g_attn[(size_t)row * AI + col] = __float2half_rn(g_suff[row * 64 + d] * inv);
}

// ================= real softmax for the last row (per head) =================
__global__ void k_lastrow(const float* __restrict__ sn, const float* __restrict__ cs) {
    __shared__ float q[64];
    __shared__ float sv[NTOK];
    __shared__ float red[16];
    __shared__ float ored[4][64];

    int h = blockIdx.x;
    int tid = threadIdx.x, w = tid >> 5, l = tid & 31;

    if (tid < 32) {
        const float* qrow = g_proj + (size_t)(NTOK - 1) * NPROJ + h * 64;
        float x1 = qrow[2 * tid] * QSCALE;
        float x2 = qrow[2 * tid + 1] * QSCALE;
        int base = (NTOK - 1) * 64;
        q[2 * tid]     = x1 * cs[base + 2 * tid]     - x2 * sn[base + 2 * tid];
        q[2 * tid + 1] = x2 * cs[base + 2 * tid + 1] + x1 * sn[base + 2 * tid + 1];
    }
    __syncthreads();

    for (int j = w; j < NTOK; j += 4) {
        const float* kr = g_proj + (size_t)j * NPROJ + COL_K;
        float p = q[l] * kr[l] + q[l + 32] * kr[l + 32];
#pragma unroll
        for (int o = 16; o; o >>= 1) p += __shfl_xor_sync(0xffffffffu, p, o);
        if (l == 0) sv[j] = p;
    }
    __syncthreads();

    float m = -1e30f;
    for (int j = tid; j < NTOK; j += 128) m = fmaxf(m, sv[j]);
#pragma unroll
    for (int o = 16; o; o >>= 1) m = fmaxf(m, __shfl_xor_sync(0xffffffffu, m, o));
    if (l == 0) red[w] = m;
    __syncthreads();
    m = fmaxf(fmaxf(red[0], red[1]), fmaxf(red[2], red[3]));
    __syncthreads();

    float ssum = 0.0f;
    for (int j = tid; j < NTOK; j += 128) {
        float p = expf(sv[j] - m);
        sv[j] = p;
        ssum += p;
    }
#pragma unroll
    for (int o = 16; o; o >>= 1) ssum += __shfl_xor_sync(0xffffffffu, ssum, o);
    if (l == 0) red[8 + w] = ssum;
    __syncthreads();
    ssum = red[8] + red[9] + red[10] + red[11];

    float o0 = 0.0f, o1 = 0.0f;
    for (int j = w; j < NTOK; j += 4) {
        const float* vr = g_proj + (size_t)j * NPROJ + COL_V;
        float p = sv[j];
        o0 += p * vr[l];
        o1 += p * vr[l + 32];
    }
    ored[w][l] = o0;
    ored[w][l + 32] = o1;
    __syncthreads();
    if (tid < 64) {
        float r = (ored[0][tid] + ored[1][tid] + ored[2][tid] + ored[3][tid]) / ssum;
        g_attn[(size_t)(NTOK - 1) * AI + h * 64 + tid] = __float2half_rn(r);
    }
}

// ================= launch =================
extern "C" void kernel_launch(void* const* d_in, const int* in_sizes, int n_in,
                              void* d_out, int out_size) {
    const float* x       = (const float*)d_in[0];
    const float* wi      = (const float*)d_in[1];
    const float* attn_wo = (const float*)d_in[2];
    const float* ff_wo   = (const float*)d_in[3];
    const float* nw      = (const float*)d_in[4];
    const float* sn      = (const float*)d_in[5];
    const float* cs      = (const float*)d_in[6];
    float* out = (float*)d_out;

    float* p_proj;
    __half *p_xn, *p_wTh, *p_wTl, *p_ffwTh, *p_ffwTl, *p_awTh, *p_awTl, *p_ffg, *p_attn;
    cudaGetSymbolAddress((void**)&p_proj, g_proj);
    cudaGetSymbolAddress((void**)&p_xn, g_xn);
    cudaGetSymbolAddress((void**)&p_wTh, g_wT_h);
    cudaGetSymbolAddress((void**)&p_wTl, g_wT_l);
    cudaGetSymbolAddress((void**)&p_ffwTh, g_ffwT_h);
    cudaGetSymbolAddress((void**)&p_ffwTl, g_ffwT_l);
    cudaGetSymbolAddress((void**)&p_awTh, g_awT_h);
    cudaGetSymbolAddress((void**)&p_awTl, g_awT_l);
    cudaGetSymbolAddress((void**)&p_ffg, g_ffg);
    cudaGetSymbolAddress((void**)&p_attn, g_attn);

    cudaFuncSetAttribute(k_tgemm<0>, cudaFuncAttributeMaxDynamicSharedMemorySize, SMEM_GEMM);
    cudaFuncSetAttribute(k_tgemm<1>, cudaFuncAttributeMaxDynamicSharedMemorySize, SMEM_GEMM);

    // 1) global-RMS layernorm -> fp16
    k_sumsq<<<256, 256>>>(x);
    k_finalize<<<1, 256>>>();
    k_norm_h<<<(NTOK * HDIM + 255) / 256, 256>>>(x, nw);

    // 2) weight transposes + hi/lo splits
    { dim3 g(NPROJ / 32, HDIM / 32); k_transplit<<<g, 256>>>(wi, p_wTh, p_wTl, HDIM, NPROJ); }
    { dim3 g(HDIM / 32, FFI / 32);   k_transplit<<<g, 256>>>(ff_wo, p_ffwTh, p_ffwTl, FFI, HDIM); }
    { dim3 g(HDIM / 32, AI / 32);    k_transplit<<<g, 256>>>(attn_wo, p_awTh, p_awTl, AI, HDIM); }

    // 3) fused projection: proj = xn @ wi  [2048 x 17536] via HMMA
    {
        dim3 g(NPROJ / 128, NTOK / 128);
        k_tgemm<0><<<g, 256, SMEM_GEMM>>>(p_xn, p_wTh, p_wTl, p_proj, NTOK, NPROJ, HDIM);
    }

    // 4) RoPE on k, swish gate, attention (suffix shortcut + real last row)
    k_rope_k<<<(NTOK * 32 + 255) / 256, 256>>>(sn, cs);
    k_swish_h<<<(NTOK * FFI + 255) / 256, 256>>>();
    k_seg_sum<<<32, 64>>>();
    k_seg_off<<<1, 64>>>();
    k_seg_suffix<<<32, 64>>>();
    k_fill_attn_h<<<((NTOK - 1) * AI + 255) / 256, 256>>>();
    k_lastrow<<<NHEADS, 128>>>(sn, cs);

    // 5) output GEMMs via HMMA: out = attn @ attn_wo ; out += ffg @ ff_wo
    {
        dim3 g(HDIM / 128, NTOK / 128);
        k_tgemm<0><<<g, 256, SMEM_GEMM>>>(p_attn, p_awTh, p_awTl, out, NTOK, HDIM, AI);
        k_tgemm<1><<<g, 256, SMEM_GEMM>>>(p_ffg, p_ffwTh, p_ffwTl, out, NTOK, HDIM, FFI);
    }
}

// round 8
// speedup vs baseline: 6.4898x; 1.6149x over previous
#include <cuda_runtime.h>
#include <cuda_fp16.h>
#include <cstdint>
#include <math.h>

#define NTOK 2048
#define HDIM 2048
#define NPROJ 17536
#define COL_K 1024
#define COL_V 1088
#define COL_FF 1152
#define COL_GATE 9344
#define FFI 8192
#define AI 1024
#define NHEADS 16
#define QSCALE 0.125f
#define LN_EPS 1e-5f

// ---------------- scratch (static device globals; no allocation) ----------------
__device__ float  g_proj[(size_t)NTOK * NPROJ];      // 143 MB fp32
__device__ __half g_xn[(size_t)NTOK * HDIM];         // normalized x, fp16
__device__ __half g_wT[(size_t)NPROJ * HDIM];        // wi^T  [17536,2048] fp16
__device__ __half g_ffwT[(size_t)HDIM * FFI];        // ff_wo^T [2048,8192] fp16
__device__ __half g_awT[(size_t)HDIM * AI];          // attn_wo^T [2048,1024] fp16
__device__ __half g_ffg[(size_t)NTOK * FFI];         // gated ff activations, fp16
__device__ __half g_attn[(size_t)NTOK * AI];         // attention output, fp16
__device__ float  g_suff[NTOK * 64];
__device__ double g_segsum[32 * 64];
__device__ double g_segoff[32 * 64];
__device__ double g_part[256];
__device__ float  g_scale;

// ---------------- helpers ----------------
__device__ __forceinline__ uint32_t smem_u32(const void* p) {
    uint32_t a;
    asm("{ .reg .u64 t; cvta.to.shared.u64 t, %1; cvt.u32.u64 %0, t; }" : "=r"(a) : "l"(p));
    return a;
}
__device__ __forceinline__ void cp16(uint32_t dst, const void* src) {
    asm volatile("cp.async.cg.shared.global [%0], [%1], 16;" :: "r"(dst), "l"(src));
}
__device__ __forceinline__ void ldsm4(uint32_t* r, uint32_t addr) {
    asm volatile("ldmatrix.sync.aligned.m8n8.x4.shared.b16 {%0,%1,%2,%3}, [%4];"
                 : "=r"(r[0]), "=r"(r[1]), "=r"(r[2]), "=r"(r[3]) : "r"(addr));
}
__device__ __forceinline__ void mma16816(float* c, const uint32_t* a, const uint32_t* b) {
    asm volatile("mma.sync.aligned.m16n8k16.row.col.f32.f16.f16.f32 "
                 "{%0,%1,%2,%3}, {%4,%5,%6,%7}, {%8,%9}, {%0,%1,%2,%3};"
                 : "+f"(c[0]), "+f"(c[1]), "+f"(c[2]), "+f"(c[3])
                 : "r"(a[0]), "r"(a[1]), "r"(a[2]), "r"(a[3]), "r"(b[0]), "r"(b[1]));
}

// ================= layernorm (global RMS scalar) =================
__global__ void k_sumsq(const float* __restrict__ x) {
    const int n = NTOK * HDIM;
    double acc = 0.0;
    for (int i = blockIdx.x * blockDim.x + threadIdx.x; i < n; i += gridDim.x * blockDim.x) {
        float v = x[i];
        acc += (double)v * (double)v;
    }
    __shared__ double s[256];
    s[threadIdx.x] = acc;
    __syncthreads();
    for (int o = 128; o > 0; o >>= 1) {
        if (threadIdx.x < o) s[threadIdx.x] += s[threadIdx.x + o];
        __syncthreads();
    }
    if (threadIdx.x == 0) g_part[blockIdx.x] = s[0];
}

__global__ void k_finalize() {
    __shared__ double s[256];
    s[threadIdx.x] = g_part[threadIdx.x];
    __syncthreads();
    for (int o = 128; o > 0; o >>= 1) {
        if (threadIdx.x < o) s[threadIdx.x] += s[threadIdx.x + o];
        __syncthreads();
    }
    if (threadIdx.x == 0) {
        double mean = s[0] / (double)(NTOK * HDIM);
        g_scale = (float)(1.0 / sqrt(mean)) + LN_EPS;
    }
}

__global__ void k_norm_h(const float* __restrict__ x, const float* __restrict__ nw) {
    int i = blockIdx.x * blockDim.x + threadIdx.x;
    if (i < NTOK * HDIM) {
        float v = x[i] * g_scale * nw[i & (HDIM - 1)];
        g_xn[i] = __float2half_rn(v);
    }
}

// ================= weight transpose: W[K,N] fp32 -> WT[N,K] fp16 =================
__global__ void k_transplit(const float* __restrict__ W, __half* __restrict__ Th,
                            int K, int N) {
    __shared__ float t[32][33];
    int n0 = blockIdx.x * 32, k0 = blockIdx.y * 32;
    int tx = threadIdx.x & 31, ty = threadIdx.x >> 5;
#pragma unroll
    for (int r = 0; r < 4; r++)
        t[ty * 4 + r][tx] = W[(size_t)(k0 + ty * 4 + r) * N + n0 + tx];
    __syncthreads();
#pragma unroll
    for (int r = 0; r < 4; r++) {
        float v = t[tx][ty * 4 + r];
        size_t o = (size_t)(n0 + ty * 4 + r) * K + k0 + tx;
        Th[o] = __float2half_rn(v);
    }
}

// ================= HMMA fp16 GEMM =================
// C[M,N] = A @ B^T, fp32 accum. A [M,K] fp16 K-major, B [N,K] fp16 K-major.
// CTA 128x128, BK=64, 8 warps (2x4), warp tile 64x32, 3-stage cp.async pipeline,
// 2 CTAs/SM (96 KB smem, <=128 regs).
#define PLANEB 16384               // 128 rows x 128B per operand tile
#define STAGEB (2 * PLANEB)        // A, B
#define NSTAGES 3
#define SMEM_GEMM (NSTAGES * STAGEB)   // 98304 bytes

__device__ __forceinline__ void load_plane(uint32_t sdst, const __half* __restrict__ g,
                                           int K, int k0, int tid) {
#pragma unroll
    for (int it = 0; it < 4; it++) {
        int idx = tid + it * 256;
        int row = idx >> 3, ch = idx & 7;
        uint32_t off = (uint32_t)(row << 7) + (uint32_t)((ch ^ (row & 7)) << 4);
        cp16(sdst + off, g + (size_t)row * K + k0 + ch * 8);
    }
}

template <int ACCUM>
__global__ void __launch_bounds__(256, 2) k_tgemm(
    const __half* __restrict__ A, const __half* __restrict__ B,
    float* __restrict__ C, int M, int N, int K)
{
    extern __shared__ char smem[];
    const uint32_t sb = smem_u32(smem);
    const int tid = threadIdx.x;
    const int lane = tid & 31, wid = tid >> 5;
    const int wm = wid & 1, wn = wid >> 1;       // warp grid 2(M) x 4(N)
    const int bm = blockIdx.y * 128, bn = blockIdx.x * 128;
    const int NC = K >> 6;

    const __half* Ap = A + (size_t)bm * K;
    const __half* Bp = B + (size_t)bn * K;

    float acc[4][4][4];
#pragma unroll
    for (int i = 0; i < 4; i++)
#pragma unroll
        for (int j = 0; j < 4; j++)
#pragma unroll
            for (int q = 0; q < 4; q++) acc[i][j][q] = 0.0f;

    // prologue: stages 0..1
#pragma unroll
    for (int s = 0; s < NSTAGES - 1; s++) {
        uint32_t st = sb + s * STAGEB;
        load_plane(st,          Ap, K, s * 64, tid);
        load_plane(st + PLANEB, Bp, K, s * 64, tid);
        asm volatile("cp.async.commit_group;" ::: "memory");
    }

    // per-thread ldmatrix address components
    int a_row[4], a_cx[4];
#pragma unroll
    for (int mt = 0; mt < 4; mt++) {
        int r = wm * 64 + mt * 16 + (lane & 15);
        a_row[mt] = r << 7;
        a_cx[mt] = r & 7;
    }
    const int a_hi = lane >> 4;
    int b_row[2], b_cx[2];
#pragma unroll
    for (int nt2 = 0; nt2 < 2; nt2++) {
        int r = wn * 32 + nt2 * 16 + (lane & 7) + ((lane >> 4) << 3);
        b_row[nt2] = r << 7;
        b_cx[nt2] = r & 7;
    }
    const int b_hi = (lane >> 3) & 1;

    for (int c = 0; c < NC; c++) {
        asm volatile("cp.async.wait_group 1;" ::: "memory");
        __syncthreads();

        if (c + NSTAGES - 1 < NC) {
            int s = (c + NSTAGES - 1) % NSTAGES;
            uint32_t st = sb + s * STAGEB;
            int k0 = (c + NSTAGES - 1) * 64;
            load_plane(st,          Ap, K, k0, tid);
            load_plane(st + PLANEB, Bp, K, k0, tid);
        }
        asm volatile("cp.async.commit_group;" ::: "memory");

        const uint32_t stA = sb + (c % NSTAGES) * STAGEB;
        const uint32_t stB = stA + PLANEB;

#pragma unroll
        for (int ks = 0; ks < 4; ks++) {
            uint32_t a[4][4], b[2][4];
#pragma unroll
            for (int mt = 0; mt < 4; mt++) {
                uint32_t addr = stA + a_row[mt] + (((ks * 2 + a_hi) ^ a_cx[mt]) << 4);
                ldsm4(a[mt], addr);
            }
#pragma unroll
            for (int nt2 = 0; nt2 < 2; nt2++) {
                uint32_t cpart = (uint32_t)(ks * 2 + b_hi);
                ldsm4(b[nt2], stB + b_row[nt2] + ((cpart ^ b_cx[nt2]) << 4));
            }
#pragma unroll
            for (int mt = 0; mt < 4; mt++)
#pragma unroll
                for (int nt = 0; nt < 4; nt++)
                    mma16816(acc[mt][nt], a[mt], &b[nt >> 1][(nt & 1) * 2]);
        }
    }
    asm volatile("cp.async.wait_group 0;" ::: "memory");

    // epilogue
    const int er = lane >> 2, ec = (lane & 3) * 2;
#pragma unroll
    for (int mt = 0; mt < 4; mt++) {
#pragma unroll
        for (int half = 0; half < 2; half++) {
            int row = bm + wm * 64 + mt * 16 + er + half * 8;
            float* cp = C + (size_t)row * N + bn + wn * 32 + ec;
#pragma unroll
            for (int nt = 0; nt < 4; nt++) {
                float2 v;
                v.x = acc[mt][nt][half * 2 + 0];
                v.y = acc[mt][nt][half * 2 + 1];
                if (ACCUM) {
                    float2 o = *(const float2*)(cp + nt * 8);
                    v.x += o.x; v.y += o.y;
                }
                *(float2*)(cp + nt * 8) = v;
            }
        }
    }
}

// ================= RoPE on k (fp32, in place in g_proj) =================
__global__ void k_rope_k(const float* __restrict__ sn, const float* __restrict__ cs) {
    int idx = blockIdx.x * blockDim.x + threadIdx.x;
    if (idx >= NTOK * 32) return;
    int row = idx >> 5, p = idx & 31;
    float* kr = g_proj + (size_t)row * NPROJ + COL_K;
    float x1 = kr[2 * p], x2 = kr[2 * p + 1];
    int base = row * 64;
    float c0 = cs[base + 2 * p],     s0 = sn[base + 2 * p];
    float c1 = cs[base + 2 * p + 1], s1 = sn[base + 2 * p + 1];
    kr[2 * p]     = x1 * c0 - x2 * s0;
    kr[2 * p + 1] = x2 * c1 + x1 * s1;
}

// ================= swish gate -> fp16 (float4 vectorized) =================
__global__ void k_swish_h() {
    int i = blockIdx.x * blockDim.x + threadIdx.x;   // NTOK * FFI / 4 threads
    if (i >= NTOK * FFI / 4) return;
    int row = i / (FFI / 4), c4 = i % (FFI / 4);
    const float* pr = g_proj + (size_t)row * NPROJ;
    float4 f = *(const float4*)(pr + COL_FF + c4 * 4);
    float4 g = *(const float4*)(pr + COL_GATE + c4 * 4);
    __half2 h0, h1;
    h0.x = __float2half_rn(f.x * (g.x / (1.0f + expf(-g.x))));
    h0.y = __float2half_rn(f.y * (g.y / (1.0f + expf(-g.y))));
    h1.x = __float2half_rn(f.z * (g.z / (1.0f + expf(-g.z))));
    h1.y = __float2half_rn(f.w * (g.w / (1.0f + expf(-g.w))));
    *(__half2*)(g_ffg + (size_t)row * FFI + c4 * 4)     = h0;
    *(__half2*)(g_ffg + (size_t)row * FFI + c4 * 4 + 2) = h1;
}

// ================= suffix scan of v (3-stage parallel) =================
// Faithful to +1e9 mask: softmax weights are exactly 1/(N-1-i) on future positions.
__global__ void k_seg_sum() {
    int s = blockIdx.x, d = threadIdx.x;
    double acc = 0.0;
    for (int j = s * 64; j < s * 64 + 64; j++)
        acc += (double)g_proj[(size_t)j * NPROJ + COL_V + d];
    g_segsum[s * 64 + d] = acc;
}
__global__ void k_seg_off() {
    int d = threadIdx.x;
    double acc = 0.0;
    for (int s = 31; s >= 0; s--) {
        g_segoff[s * 64 + d] = acc;
        acc += g_segsum[s * 64 + d];
    }
}
__global__ void k_seg_suffix() {
    int s = blockIdx.x, d = threadIdx.x;
    double acc = g_segoff[s * 64 + d];
    for (int j = s * 64 + 63; j >= s * 64; j--) {
        acc += (double)g_proj[(size_t)j * NPROJ + COL_V + d];
        if (j >= 1) g_suff[(j - 1) * 64 + d] = (float)acc;
    }
}

__global__ void k_fill_attn_h() {
    int idx = blockIdx.x * blockDim.x + threadIdx.x;
    if (idx >= (NTOK - 1) * AI) return;
    int row = idx >> 10, col = idx & (AI - 1);
    int d = col & 63;
    float inv = 1.0f / (float)(NTOK - 1 - row);
    g_attn[(size_t)row * AI + col] = __float2half_rn(g_suff[row * 64 + d] * inv);
}

// ================= real softmax for the last row (per head) =================
__global__ void k_lastrow(const float* __restrict__ sn, const float* __restrict__ cs) {
    __shared__ float q[64];
    __shared__ float sv[NTOK];
    __shared__ float red[16];
    __shared__ float ored[4][64];

    int h = blockIdx.x;
    int tid = threadIdx.x, w = tid >> 5, l = tid & 31;

    if (tid < 32) {
        const float* qrow = g_proj + (size_t)(NTOK - 1) * NPROJ + h * 64;
        float x1 = qrow[2 * tid] * QSCALE;
        float x2 = qrow[2 * tid + 1] * QSCALE;
        int base = (NTOK - 1) * 64;
        q[2 * tid]     = x1 * cs[base + 2 * tid]     - x2 * sn[base + 2 * tid];
        q[2 * tid + 1] = x2 * cs[base + 2 * tid + 1] + x1 * sn[base + 2 * tid + 1];
    }
    __syncthreads();

    for (int j = w; j < NTOK; j += 4) {
        const float* kr = g_proj + (size_t)j * NPROJ + COL_K;
        float p = q[l] * kr[l] + q[l + 32] * kr[l + 32];
#pragma unroll
        for (int o = 16; o; o >>= 1) p += __shfl_xor_sync(0xffffffffu, p, o);
        if (l == 0) sv[j] = p;
    }
    __syncthreads();

    float m = -1e30f;
    for (int j = tid; j < NTOK; j += 128) m = fmaxf(m, sv[j]);
#pragma unroll
    for (int o = 16; o; o >>= 1) m = fmaxf(m, __shfl_xor_sync(0xffffffffu, m, o));
    if (l == 0) red[w] = m;
    __syncthreads();
    m = fmaxf(fmaxf(red[0], red[1]), fmaxf(red[2], red[3]));
    __syncthreads();

    float ssum = 0.0f;
    for (int j = tid; j < NTOK; j += 128) {
        float p = expf(sv[j] - m);
        sv[j] = p;
        ssum += p;
    }
#pragma unroll
    for (int o = 16; o; o >>= 1) ssum += __shfl_xor_sync(0xffffffffu, ssum, o);
    if (l == 0) red[8 + w] = ssum;
    __syncthreads();
    ssum = red[8] + red[9] + red[10] + red[11];

    float o0 = 0.0f, o1 = 0.0f;
    for (int j = w; j < NTOK; j += 4) {
        const float* vr = g_proj + (size_t)j * NPROJ + COL_V;
        float p = sv[j];
        o0 += p * vr[l];
        o1 += p * vr[l + 32];
    }
    ored[w][l] = o0;
    ored[w][l + 32] = o1;
    __syncthreads();
    if (tid < 64) {
        float r = (ored[0][tid] + ored[1][tid] + ored[2][tid] + ored[3][tid]) / ssum;
        g_attn[(size_t)(NTOK - 1) * AI + h * 64 + tid] = __float2half_rn(r);
    }
}

// ================= launch =================
extern "C" void kernel_launch(void* const* d_in, const int* in_sizes, int n_in,
                              void* d_out, int out_size) {
    const float* x       = (const float*)d_in[0];
    const float* wi      = (const float*)d_in[1];
    const float* attn_wo = (const float*)d_in[2];
    const float* ff_wo   = (const float*)d_in[3];
    const float* nw      = (const float*)d_in[4];
    const float* sn      = (const float*)d_in[5];
    const float* cs      = (const float*)d_in[6];
    float* out = (float*)d_out;

    float* p_proj;
    __half *p_xn, *p_wT, *p_ffwT, *p_awT, *p_ffg, *p_attn;
    cudaGetSymbolAddress((void**)&p_proj, g_proj);
    cudaGetSymbolAddress((void**)&p_xn, g_xn);
    cudaGetSymbolAddress((void**)&p_wT, g_wT);
    cudaGetSymbolAddress((void**)&p_ffwT, g_ffwT);
    cudaGetSymbolAddress((void**)&p_awT, g_awT);
    cudaGetSymbolAddress((void**)&p_ffg, g_ffg);
    cudaGetSymbolAddress((void**)&p_attn, g_attn);

    cudaFuncSetAttribute(k_tgemm<0>, cudaFuncAttributeMaxDynamicSharedMemorySize, SMEM_GEMM);
    cudaFuncSetAttribute(k_tgemm<1>, cudaFuncAttributeMaxDynamicSharedMemorySize, SMEM_GEMM);

    // 1) global-RMS layernorm -> fp16
    k_sumsq<<<256, 256>>>(x);
    k_finalize<<<1, 256>>>();
    k_norm_h<<<(NTOK * HDIM + 255) / 256, 256>>>(x, nw);

    // 2) weight transposes -> fp16
    { dim3 g(NPROJ / 32, HDIM / 32); k_transplit<<<g, 256>>>(wi, p_wT, HDIM, NPROJ); }
    { dim3 g(HDIM / 32, FFI / 32);   k_transplit<<<g, 256>>>(ff_wo, p_ffwT, FFI, HDIM); }
    { dim3 g(HDIM / 32, AI / 32);    k_transplit<<<g, 256>>>(attn_wo, p_awT, AI, HDIM); }

    // 3) fused projection: proj = xn @ wi  [2048 x 17536] via HMMA
    {
        dim3 g(NPROJ / 128, NTOK / 128);
        k_tgemm<0><<<g, 256, SMEM_GEMM>>>(p_xn, p_wT, p_proj, NTOK, NPROJ, HDIM);
    }

    // 4) RoPE on k, swish gate, attention (suffix shortcut + real last row)
    k_rope_k<<<(NTOK * 32 + 255) / 256, 256>>>(sn, cs);
    k_swish_h<<<(NTOK * FFI / 4 + 255) / 256, 256>>>();
    k_seg_sum<<<32, 64>>>();
    k_seg_off<<<1, 64>>>();
    k_seg_suffix<<<32, 64>>>();
    k_fill_attn_h<<<((NTOK - 1) * AI + 255) / 256, 256>>>();
    k_lastrow<<<NHEADS, 128>>>(sn, cs);

    // 5) output GEMMs via HMMA: out = attn @ attn_wo ; out += ffg @ ff_wo
    {
        dim3 g(HDIM / 128, NTOK / 128);
        k_tgemm<0><<<g, 256, SMEM_GEMM>>>(p_attn, p_awT, out, NTOK, HDIM, AI);
        k_tgemm<1><<<g, 256, SMEM_GEMM>>>(p_ffg, p_ffwT, out, NTOK, HDIM, FFI);
    }
}